// round 4
// baseline (speedup 1.0000x reference)
#include <cuda_runtime.h>
#include <cuda_bf16.h>
#include <math.h>

// Problem constants
#define BB   2
#define SS   2048
#define EE   1024
#define HH   16
#define HD   64
#define C3   3072          // 3*E
#define MTOK (BB*SS)       // 4096 tokens

// Scratch (static device globals — allocation-guard safe)
__device__ float g_qkv[(size_t)MTOK * C3];   // [4096, 3072] interleaved per head [q|k|v]
__device__ float g_att[(size_t)MTOK * EE];   // [4096, 1024] merged-head attention output

// ---------------------------------------------------------------------------
// SGEMM: C[M,N] = A[M,K] @ B[K,N] + bias[N]   (fp32, 128x128x16 tile, 8x8/thread)
// ---------------------------------------------------------------------------
__global__ __launch_bounds__(256, 2)
void sgemm_bias_kernel(const float* __restrict__ A, const float* __restrict__ B,
                       const float* __restrict__ bias, float* __restrict__ C,
                       int M, int N, int K)
{
    constexpr int BM = 128, BN = 128, BK = 16;
    __shared__ float As[BK][BM + 1];   // transposed A tile, +1 pad
    __shared__ float Bs[BK][BN];

    const int tid = threadIdx.x;
    const int tx = tid & 15;           // 0..15 -> output col group
    const int ty = tid >> 4;           // 0..15 -> output row group
    const int brow = blockIdx.y * BM;
    const int bcol = blockIdx.x * BN;

    const int aRow = tid >> 2;         // 0..63
    const int aCol = (tid & 3) << 2;   // 0,4,8,12
    const int bRow = tid >> 5;         // 0..7
    const int bCol = (tid & 31) << 2;  // 0..124

    float acc[8][8] = {};

    for (int k0 = 0; k0 < K; k0 += BK) {
        // Load A tile (128x16), store transposed
        #pragma unroll
        for (int i = 0; i < 2; i++) {
            const float4 v = *reinterpret_cast<const float4*>(
                &A[(size_t)(brow + aRow + i * 64) * K + k0 + aCol]);
            As[aCol + 0][aRow + i * 64] = v.x;
            As[aCol + 1][aRow + i * 64] = v.y;
            As[aCol + 2][aRow + i * 64] = v.z;
            As[aCol + 3][aRow + i * 64] = v.w;
        }
        // Load B tile (16x128)
        #pragma unroll
        for (int i = 0; i < 2; i++) {
            const float4 v = *reinterpret_cast<const float4*>(
                &B[(size_t)(k0 + bRow + i * 8) * N + bcol + bCol]);
            *reinterpret_cast<float4*>(&Bs[bRow + i * 8][bCol]) = v;
        }
        __syncthreads();

        #pragma unroll
        for (int kk = 0; kk < BK; kk++) {
            float af[8], bf[8];
            #pragma unroll
            for (int i = 0; i < 8; i++) af[i] = As[kk][ty * 8 + i];
            const float4 b0 = *reinterpret_cast<const float4*>(&Bs[kk][tx * 8]);
            const float4 b1 = *reinterpret_cast<const float4*>(&Bs[kk][tx * 8 + 4]);
            bf[0] = b0.x; bf[1] = b0.y; bf[2] = b0.z; bf[3] = b0.w;
            bf[4] = b1.x; bf[5] = b1.y; bf[6] = b1.z; bf[7] = b1.w;
            #pragma unroll
            for (int i = 0; i < 8; i++)
                #pragma unroll
                for (int j = 0; j < 8; j++)
                    acc[i][j] = fmaf(af[i], bf[j], acc[i][j]);
        }
        __syncthreads();
    }

    // Epilogue: add bias, vectorized store
    #pragma unroll
    for (int i = 0; i < 8; i++) {
        const size_t r = (size_t)(brow + ty * 8 + i);
        #pragma unroll
        for (int j = 0; j < 8; j += 4) {
            const int c = bcol + tx * 8 + j;
            float4 o;
            o.x = acc[i][j + 0] + bias[c + 0];
            o.y = acc[i][j + 1] + bias[c + 1];
            o.z = acc[i][j + 2] + bias[c + 2];
            o.w = acc[i][j + 3] + bias[c + 3];
            *reinterpret_cast<float4*>(&C[r * N + c]) = o;
        }
    }
}

// ---------------------------------------------------------------------------
// Fused causal flash attention (fp32).
// Grid: (S/64, H, B). Block: 256 threads. Thread (row = tid/4, cg = tid%4)
// owns query row `row` (local) and 16 output columns [cg*16, cg*16+16).
// qkv layout per token: head h occupies cols [h*192, h*192+192) = [q|k|v].
// ---------------------------------------------------------------------------
__global__ __launch_bounds__(256, 2)
void attn_kernel(const float* __restrict__ qkv, float* __restrict__ out)
{
    const int qb = gridDim.x - 1 - blockIdx.x;   // heavy blocks first
    const int h  = blockIdx.y;
    const int b  = blockIdx.z;

    extern __shared__ float sm[];
    float4* __restrict__ Ks4 = reinterpret_cast<float4*>(sm);  // 64 cols x 17 f4 (stride 68 floats), XOR-swizzled
    float*  __restrict__ Vs  = sm + 64 * 68;                   // [64][64]
    float*  __restrict__ Ps  = Vs + 64 * 64;                   // [64][65]

    const int tid = threadIdx.x;
    const int row = tid >> 2;       // 0..63
    const int cg  = tid & 3;        // 0..3
    const int c0  = cg << 4;        // 16-col group base

    // Load this thread's Q row into registers (64 floats = 16 float4)
    const float* qptr = qkv + ((size_t)(b * SS + qb * 64 + row)) * C3 + h * 192;
    float4 qreg[16];
    #pragma unroll
    for (int d4 = 0; d4 < 16; d4++)
        qreg[d4] = *reinterpret_cast<const float4*>(qptr + d4 * 4);

    float m_i = -INFINITY, l_i = 0.f;
    float acc[16];
    #pragma unroll
    for (int i = 0; i < 16; i++) acc[i] = 0.f;

    for (int j = 0; j <= qb; j++) {
        // ---- Load K/V tile (64 tokens x 64 dims each) ----
        const size_t base_kv = ((size_t)(b * SS + j * 64)) * C3 + h * 192;
        for (int g = tid; g < 64 * 16; g += 256) {
            const int r  = g >> 4;
            const int c4 = g & 15;
            const float* src = qkv + base_kv + (size_t)r * C3;
            const float4 kv = *reinterpret_cast<const float4*>(src + 64 + c4 * 4);
            Ks4[r * 17 + (c4 ^ ((r >> 4) & 3))] = kv;   // swizzle by col-group
            const float4 vv = *reinterpret_cast<const float4*>(src + 128 + c4 * 4);
            *reinterpret_cast<float4*>(&Vs[r * 64 + c4 * 4]) = vv;
        }
        __syncthreads();

        // ---- Scores for this thread's 16 columns ----
        float lm = -INFINITY;
        const bool diag = (j == qb);
        #pragma unroll 4
        for (int i = 0; i < 16; i++) {
            const int col = c0 + i;
            float sum = 0.f;
            const float4* kcol = Ks4 + col * 17;
            #pragma unroll
            for (int d4 = 0; d4 < 16; d4++) {
                const float4 k4 = kcol[d4 ^ cg];       // conflict-free via swizzle
                sum = fmaf(qreg[d4].x, k4.x, sum);
                sum = fmaf(qreg[d4].y, k4.y, sum);
                sum = fmaf(qreg[d4].z, k4.z, sum);
                sum = fmaf(qreg[d4].w, k4.w, sum);
            }
            sum *= 0.125f;                              // 1/sqrt(64)
            if (diag && col > row) sum = -INFINITY;     // exp-underflow == -10000 path
            lm = fmaxf(lm, sum);
            Ps[row * 65 + col] = sum;
        }

        // ---- Online softmax (quad all-reduce over 4 lanes of this row) ----
        lm = fmaxf(lm, __shfl_xor_sync(0xFFFFFFFFu, lm, 1));
        lm = fmaxf(lm, __shfl_xor_sync(0xFFFFFFFFu, lm, 2));
        const float new_m = fmaxf(m_i, lm);
        const float corr = __expf(m_i - new_m);
        l_i *= corr;
        #pragma unroll
        for (int i = 0; i < 16; i++) acc[i] *= corr;

        float psum = 0.f;
        #pragma unroll
        for (int i = 0; i < 16; i++) {
            float p = __expf(Ps[row * 65 + c0 + i] - new_m);  // exp(-inf)=0 for masked
            Ps[row * 65 + c0 + i] = p;
            psum += p;
        }
        psum += __shfl_xor_sync(0xFFFFFFFFu, psum, 1);
        psum += __shfl_xor_sync(0xFFFFFFFFu, psum, 2);
        l_i += psum;
        m_i = new_m;
        __syncwarp();   // Ps row written by this quad (same warp) before AV reads

        // ---- acc += P @ V ----
        #pragma unroll 8
        for (int k = 0; k < 64; k++) {
            const float p = Ps[row * 65 + k];
            const float4 v0 = *reinterpret_cast<const float4*>(&Vs[k * 64 + c0]);
            const float4 v1 = *reinterpret_cast<const float4*>(&Vs[k * 64 + c0 + 4]);
            const float4 v2 = *reinterpret_cast<const float4*>(&Vs[k * 64 + c0 + 8]);
            const float4 v3 = *reinterpret_cast<const float4*>(&Vs[k * 64 + c0 + 12]);
            acc[0]  = fmaf(p, v0.x, acc[0]);  acc[1]  = fmaf(p, v0.y, acc[1]);
            acc[2]  = fmaf(p, v0.z, acc[2]);  acc[3]  = fmaf(p, v0.w, acc[3]);
            acc[4]  = fmaf(p, v1.x, acc[4]);  acc[5]  = fmaf(p, v1.y, acc[5]);
            acc[6]  = fmaf(p, v1.z, acc[6]);  acc[7]  = fmaf(p, v1.w, acc[7]);
            acc[8]  = fmaf(p, v2.x, acc[8]);  acc[9]  = fmaf(p, v2.y, acc[9]);
            acc[10] = fmaf(p, v2.z, acc[10]); acc[11] = fmaf(p, v2.w, acc[11]);
            acc[12] = fmaf(p, v3.x, acc[12]); acc[13] = fmaf(p, v3.y, acc[13]);
            acc[14] = fmaf(p, v3.z, acc[14]); acc[15] = fmaf(p, v3.w, acc[15]);
        }
        __syncthreads();   // all warps done with Ks/Vs before next tile load
    }

    // ---- Normalize and write merged-head output [token, h*64 + col] ----
    const float rl = 1.f / l_i;
    const size_t t = (size_t)(b * SS + qb * 64 + row);
    float* dst = out + t * EE + h * HD + c0;
    #pragma unroll
    for (int i = 0; i < 16; i += 4) {
        float4 o;
        o.x = acc[i + 0] * rl; o.y = acc[i + 1] * rl;
        o.z = acc[i + 2] * rl; o.w = acc[i + 3] * rl;
        *reinterpret_cast<float4*>(dst + i) = o;
    }
}

// ---------------------------------------------------------------------------
extern "C" void kernel_launch(void* const* d_in, const int* in_sizes, int n_in,
                              void* d_out, int out_size)
{
    const float* x  = (const float*)d_in[0];  // hidden_states [2,2048,1024]
    const float* Wa = (const float*)d_in[1];  // W_attn [1024,3072]
    const float* ba = (const float*)d_in[2];  // b_attn [3072]
    const float* Wp = (const float*)d_in[3];  // W_proj [1024,1024]
    const float* bp = (const float*)d_in[4];  // b_proj [1024]
    float* out = (float*)d_out;               // [2,2048,1024]

    float *qkv, *att;
    cudaGetSymbolAddress((void**)&qkv, g_qkv);
    cudaGetSymbolAddress((void**)&att, g_att);

    // 1) QKV projection
    sgemm_bias_kernel<<<dim3(C3 / 128, MTOK / 128), 256>>>(x, Wa, ba, qkv, MTOK, C3, EE);

    // 2) Fused causal attention
    const size_t shmem = (size_t)(64 * 68 + 64 * 64 + 64 * 65) * sizeof(float); // 50432 B
    cudaFuncSetAttribute(attn_kernel, cudaFuncAttributeMaxDynamicSharedMemorySize, (int)shmem);
    attn_kernel<<<dim3(SS / 64, HH, BB), 256, shmem>>>(qkv, att);

    // 3) Output projection
    sgemm_bias_kernel<<<dim3(EE / 128, MTOK / 128), 256>>>(att, Wp, bp, out, MTOK, EE, EE);
}

// round 5
// speedup vs baseline: 2.5403x; 2.5403x over previous
#include <cuda_runtime.h>
#include <cuda_bf16.h>
#include <math.h>
#include <stdint.h>

// Problem constants
#define BB   2
#define SS   2048
#define EE   1024
#define HH   16
#define HD   64
#define C3   3072          // 3*E
#define MTOK (BB*SS)       // 4096 tokens

// Scratch (static device globals — allocation-guard safe)
__device__ float g_qkv[(size_t)MTOK * C3];   // [4096, 3072] interleaved per head [q|k|v]
__device__ float g_att[(size_t)MTOK * EE];   // [4096, 1024] merged-head attention output

// ---------------------------------------------------------------------------
// SGEMM: C[M,N] = A[M,K] @ B[K,N] + bias[N]   (fp32, 128x128x16 tile, 8x8/thread)
// (unchanged from passing round)
// ---------------------------------------------------------------------------
__global__ __launch_bounds__(256, 2)
void sgemm_bias_kernel(const float* __restrict__ A, const float* __restrict__ B,
                       const float* __restrict__ bias, float* __restrict__ C,
                       int M, int N, int K)
{
    constexpr int BM = 128, BN = 128, BK = 16;
    __shared__ float As[BK][BM + 1];
    __shared__ float Bs[BK][BN];

    const int tid = threadIdx.x;
    const int tx = tid & 15;
    const int ty = tid >> 4;
    const int brow = blockIdx.y * BM;
    const int bcol = blockIdx.x * BN;

    const int aRow = tid >> 2;
    const int aCol = (tid & 3) << 2;
    const int bRow = tid >> 5;
    const int bCol = (tid & 31) << 2;

    float acc[8][8] = {};

    for (int k0 = 0; k0 < K; k0 += BK) {
        #pragma unroll
        for (int i = 0; i < 2; i++) {
            const float4 v = *reinterpret_cast<const float4*>(
                &A[(size_t)(brow + aRow + i * 64) * K + k0 + aCol]);
            As[aCol + 0][aRow + i * 64] = v.x;
            As[aCol + 1][aRow + i * 64] = v.y;
            As[aCol + 2][aRow + i * 64] = v.z;
            As[aCol + 3][aRow + i * 64] = v.w;
        }
        #pragma unroll
        for (int i = 0; i < 2; i++) {
            const float4 v = *reinterpret_cast<const float4*>(
                &B[(size_t)(k0 + bRow + i * 8) * N + bcol + bCol]);
            *reinterpret_cast<float4*>(&Bs[bRow + i * 8][bCol]) = v;
        }
        __syncthreads();

        #pragma unroll
        for (int kk = 0; kk < BK; kk++) {
            float af[8], bf[8];
            #pragma unroll
            for (int i = 0; i < 8; i++) af[i] = As[kk][ty * 8 + i];
            const float4 b0 = *reinterpret_cast<const float4*>(&Bs[kk][tx * 8]);
            const float4 b1 = *reinterpret_cast<const float4*>(&Bs[kk][tx * 8 + 4]);
            bf[0] = b0.x; bf[1] = b0.y; bf[2] = b0.z; bf[3] = b0.w;
            bf[4] = b1.x; bf[5] = b1.y; bf[6] = b1.z; bf[7] = b1.w;
            #pragma unroll
            for (int i = 0; i < 8; i++)
                #pragma unroll
                for (int j = 0; j < 8; j++)
                    acc[i][j] = fmaf(af[i], bf[j], acc[i][j]);
        }
        __syncthreads();
    }

    #pragma unroll
    for (int i = 0; i < 8; i++) {
        const size_t r = (size_t)(brow + ty * 8 + i);
        #pragma unroll
        for (int j = 0; j < 8; j += 4) {
            const int c = bcol + tx * 8 + j;
            float4 o;
            o.x = acc[i][j + 0] + bias[c + 0];
            o.y = acc[i][j + 1] + bias[c + 1];
            o.z = acc[i][j + 2] + bias[c + 2];
            o.w = acc[i][j + 3] + bias[c + 3];
            *reinterpret_cast<float4*>(&C[r * N + c]) = o;
        }
    }
}

// ---------------------------------------------------------------------------
// tf32 helpers
// ---------------------------------------------------------------------------
__device__ __forceinline__ float f2tf32(float f) {
    uint32_t u;
    asm("cvt.rna.tf32.f32 %0, %1;" : "=r"(u) : "f"(f));
    return __uint_as_float(u);
}

__device__ __forceinline__ void mma_tf32(float* d, const uint32_t* a,
                                         uint32_t b0, uint32_t b1) {
    asm volatile(
        "mma.sync.aligned.m16n8k8.row.col.f32.tf32.tf32.f32 "
        "{%0,%1,%2,%3}, {%4,%5,%6,%7}, {%8,%9}, {%0,%1,%2,%3};"
        : "+f"(d[0]), "+f"(d[1]), "+f"(d[2]), "+f"(d[3])
        : "r"(a[0]), "r"(a[1]), "r"(a[2]), "r"(a[3]), "r"(b0), "r"(b1));
}

// ---------------------------------------------------------------------------
// Tensor-core flash attention (tf32 mma, fp32 softmax state).
// Grid: (S/64, H, B). Block: 128 threads = 4 warps; warp w owns query rows
// [w*16, w*16+16) of the 64-query block. Key tiles of 64 tokens.
// Smem tiles K,V,P: [64][76] floats (stride 76 -> conflict-free frag loads).
// ---------------------------------------------------------------------------
#define KST 76

__global__ __launch_bounds__(128, 2)
void attn_tc_kernel(const float* __restrict__ qkv, float* __restrict__ out)
{
    const int qb = gridDim.x - 1 - blockIdx.x;   // heavy blocks first
    const int h  = blockIdx.y;
    const int b  = blockIdx.z;

    extern __shared__ float sm[];
    float* Ks = sm;                 // [64][76]
    float* Vs = Ks + 64 * KST;      // [64][76]
    float* Ps = Vs + 64 * KST;      // [64][76]  (Q staging, then P per warp)

    const int tid  = threadIdx.x;
    const int w    = tid >> 5;
    const int lane = tid & 31;
    const int gq   = lane >> 2;     // group id (0..7)
    const int tq   = lane & 3;      // thread-in-group (0..3)

    const size_t tok0 = (size_t)(b * SS + qb * 64);

    // ---- Stage Q (tf32-rounded) into Ps, then load A-fragments ----
    #pragma unroll
    for (int it = 0; it < 8; it++) {
        const int idx = tid + it * 128;
        const int r = idx >> 4, c4 = (idx & 15) << 2;
        const float4 v = *reinterpret_cast<const float4*>(
            qkv + (tok0 + r) * C3 + h * 192 + c4);
        float* d = Ps + r * KST + c4;
        d[0] = f2tf32(v.x); d[1] = f2tf32(v.y);
        d[2] = f2tf32(v.z); d[3] = f2tf32(v.w);
    }
    __syncthreads();

    uint32_t qf[8][4];
    #pragma unroll
    for (int k = 0; k < 8; k++) {
        const float* base = Ps + (w * 16) * KST + k * 8 + tq;
        qf[k][0] = __float_as_uint(base[gq * KST]);
        qf[k][1] = __float_as_uint(base[(gq + 8) * KST]);
        qf[k][2] = __float_as_uint(base[gq * KST + 4]);
        qf[k][3] = __float_as_uint(base[(gq + 8) * KST + 4]);
    }
    // (warp w only ever touches Ps rows [w*16, w*16+16) from here on)

    float m0 = -1e30f, m1 = -1e30f, l0 = 0.f, l1 = 0.f;
    float o[8][4];
    #pragma unroll
    for (int n = 0; n < 8; n++) { o[n][0]=o[n][1]=o[n][2]=o[n][3]=0.f; }

    const int rowA = w * 16 + gq;      // local row of c0/c1
    const int rowB = rowA + 8;         // local row of c2/c3

    for (int j = 0; j <= qb; j++) {
        __syncthreads();   // prior AV reads of Ks/Vs complete before overwrite
        // ---- Load K/V tile (tf32-rounded) ----
        const size_t kt0 = (size_t)(b * SS + j * 64);
        #pragma unroll
        for (int it = 0; it < 8; it++) {
            const int idx = tid + it * 128;
            const int r = idx >> 4, c4 = (idx & 15) << 2;
            const float* src = qkv + (kt0 + r) * C3 + h * 192;
            const float4 kv = *reinterpret_cast<const float4*>(src + 64 + c4);
            float* dk = Ks + r * KST + c4;
            dk[0] = f2tf32(kv.x); dk[1] = f2tf32(kv.y);
            dk[2] = f2tf32(kv.z); dk[3] = f2tf32(kv.w);
            const float4 vv = *reinterpret_cast<const float4*>(src + 128 + c4);
            float* dv = Vs + r * KST + c4;
            dv[0] = f2tf32(vv.x); dv[1] = f2tf32(vv.y);
            dv[2] = f2tf32(vv.z); dv[3] = f2tf32(vv.w);
        }
        __syncthreads();

        const bool diag = (j == qb);
        const int  nmax = diag ? (2 * w + 1) : 7;

        // ---- S = Q @ K^T for this warp's 16 rows x 64 keys ----
        float s[8][4];
        #pragma unroll
        for (int n = 0; n < 8; n++) { s[n][0]=s[n][1]=s[n][2]=s[n][3]=0.f; }
        for (int n = 0; n <= nmax; n++) {
            const float* kb = Ks + (n * 8 + gq) * KST + tq;
            #pragma unroll
            for (int k = 0; k < 8; k++) {
                const uint32_t b0 = __float_as_uint(kb[k * 8]);
                const uint32_t b1 = __float_as_uint(kb[k * 8 + 4]);
                mma_tf32(s[n], qf[k], b0, b1);
            }
        }

        // ---- scale + causal mask + row max ----
        float mx0 = -1e30f, mx1 = -1e30f;
        for (int n = 0; n <= nmax; n++) {
            s[n][0] *= 0.125f; s[n][1] *= 0.125f;
            s[n][2] *= 0.125f; s[n][3] *= 0.125f;
            if (diag) {
                const int col = n * 8 + 2 * tq;
                if (col     > rowA) s[n][0] = -1e30f;
                if (col + 1 > rowA) s[n][1] = -1e30f;
                if (col     > rowB) s[n][2] = -1e30f;
                if (col + 1 > rowB) s[n][3] = -1e30f;
            }
            mx0 = fmaxf(mx0, fmaxf(s[n][0], s[n][1]));
            mx1 = fmaxf(mx1, fmaxf(s[n][2], s[n][3]));
        }
        mx0 = fmaxf(mx0, __shfl_xor_sync(0xFFFFFFFFu, mx0, 1));
        mx0 = fmaxf(mx0, __shfl_xor_sync(0xFFFFFFFFu, mx0, 2));
        mx1 = fmaxf(mx1, __shfl_xor_sync(0xFFFFFFFFu, mx1, 1));
        mx1 = fmaxf(mx1, __shfl_xor_sync(0xFFFFFFFFu, mx1, 2));

        const float nm0 = fmaxf(m0, mx0), nm1 = fmaxf(m1, mx1);
        const float cf0 = __expf(m0 - nm0), cf1 = __expf(m1 - nm1);
        l0 *= cf0; l1 *= cf1;
        #pragma unroll
        for (int n = 0; n < 8; n++) {
            o[n][0] *= cf0; o[n][1] *= cf0;
            o[n][2] *= cf1; o[n][3] *= cf1;
        }

        // ---- P = exp(S - m), write tf32 P to smem ----
        float ps0 = 0.f, ps1 = 0.f;
        for (int n = 0; n <= nmax; n++) {
            const float p0 = __expf(s[n][0] - nm0);
            const float p1 = __expf(s[n][1] - nm0);
            const float p2 = __expf(s[n][2] - nm1);
            const float p3 = __expf(s[n][3] - nm1);
            ps0 += p0 + p1; ps1 += p2 + p3;
            float2 lo; lo.x = f2tf32(p0); lo.y = f2tf32(p1);
            float2 hi; hi.x = f2tf32(p2); hi.y = f2tf32(p3);
            *reinterpret_cast<float2*>(Ps + rowA * KST + n * 8 + 2 * tq) = lo;
            *reinterpret_cast<float2*>(Ps + rowB * KST + n * 8 + 2 * tq) = hi;
        }
        ps0 += __shfl_xor_sync(0xFFFFFFFFu, ps0, 1);
        ps0 += __shfl_xor_sync(0xFFFFFFFFu, ps0, 2);
        ps1 += __shfl_xor_sync(0xFFFFFFFFu, ps1, 1);
        ps1 += __shfl_xor_sync(0xFFFFFFFFu, ps1, 2);
        l0 += ps0; l1 += ps1; m0 = nm0; m1 = nm1;
        __syncwarp();   // P visible to all lanes of this warp

        // ---- O += P @ V ----
        for (int k = 0; k <= nmax; k++) {
            const float* pb = Ps + (w * 16) * KST + k * 8 + tq;
            uint32_t pa[4];
            pa[0] = __float_as_uint(pb[gq * KST]);
            pa[1] = __float_as_uint(pb[(gq + 8) * KST]);
            pa[2] = __float_as_uint(pb[gq * KST + 4]);
            pa[3] = __float_as_uint(pb[(gq + 8) * KST + 4]);
            const float* vb = Vs + (k * 8 + tq) * KST + gq;
            #pragma unroll
            for (int n = 0; n < 8; n++) {
                const uint32_t b0 = __float_as_uint(vb[n * 8]);
                const uint32_t b1 = __float_as_uint(vb[4 * KST + n * 8]);
                mma_tf32(o[n], pa, b0, b1);
            }
        }
    }

    // ---- Normalize + write merged-head output ----
    const float i0 = 1.f / l0, i1 = 1.f / l1;
    float* dstA = out + (tok0 + rowA) * EE + h * HD;
    float* dstB = out + (tok0 + rowB) * EE + h * HD;
    #pragma unroll
    for (int n = 0; n < 8; n++) {
        float2 a; a.x = o[n][0] * i0; a.y = o[n][1] * i0;
        float2 c; c.x = o[n][2] * i1; c.y = o[n][3] * i1;
        *reinterpret_cast<float2*>(dstA + n * 8 + 2 * tq) = a;
        *reinterpret_cast<float2*>(dstB + n * 8 + 2 * tq) = c;
    }
}

// ---------------------------------------------------------------------------
extern "C" void kernel_launch(void* const* d_in, const int* in_sizes, int n_in,
                              void* d_out, int out_size)
{
    const float* x  = (const float*)d_in[0];  // hidden_states [2,2048,1024]
    const float* Wa = (const float*)d_in[1];  // W_attn [1024,3072]
    const float* ba = (const float*)d_in[2];  // b_attn [3072]
    const float* Wp = (const float*)d_in[3];  // W_proj [1024,1024]
    const float* bp = (const float*)d_in[4];  // b_proj [1024]
    float* out = (float*)d_out;               // [2,2048,1024]

    float *qkv, *att;
    cudaGetSymbolAddress((void**)&qkv, g_qkv);
    cudaGetSymbolAddress((void**)&att, g_att);

    // 1) QKV projection
    sgemm_bias_kernel<<<dim3(C3 / 128, MTOK / 128), 256>>>(x, Wa, ba, qkv, MTOK, C3, EE);

    // 2) Tensor-core fused causal attention
    const size_t shmem = (size_t)(3 * 64 * KST) * sizeof(float);  // 58368 B
    cudaFuncSetAttribute(attn_tc_kernel, cudaFuncAttributeMaxDynamicSharedMemorySize, (int)shmem);
    attn_tc_kernel<<<dim3(SS / 64, HH, BB), 128, shmem>>>(qkv, att);

    // 3) Output projection
    sgemm_bias_kernel<<<dim3(EE / 128, MTOK / 128), 256>>>(att, Wp, bp, out, MTOK, EE, EE);
}

// round 6
// speedup vs baseline: 3.5555x; 1.3996x over previous
#include <cuda_runtime.h>
#include <cuda_bf16.h>
#include <math.h>
#include <stdint.h>

// Problem constants
#define BB   2
#define SS   2048
#define EE   1024
#define HH   16
#define HD   64
#define C3   3072          // 3*E
#define MTOK (BB*SS)       // 4096 tokens

// Scratch (static device globals — allocation-guard safe)
__device__ float g_qkv[(size_t)MTOK * C3];   // [4096, 3072] interleaved per head [q|k|v]
__device__ float g_att[(size_t)MTOK * EE];   // [4096, 1024] merged-head attention output

// ---------------------------------------------------------------------------
// tf32 helpers
// ---------------------------------------------------------------------------
__device__ __forceinline__ float f2tf32(float f) {
    uint32_t u;
    asm("cvt.rna.tf32.f32 %0, %1;" : "=r"(u) : "f"(f));
    return __uint_as_float(u);
}

__device__ __forceinline__ void mma_tf32(float* d, const uint32_t* a,
                                         uint32_t b0, uint32_t b1) {
    asm volatile(
        "mma.sync.aligned.m16n8k8.row.col.f32.tf32.tf32.f32 "
        "{%0,%1,%2,%3}, {%4,%5,%6,%7}, {%8,%9}, {%0,%1,%2,%3};"
        : "+f"(d[0]), "+f"(d[1]), "+f"(d[2]), "+f"(d[3])
        : "r"(a[0]), "r"(a[1]), "r"(a[2]), "r"(a[3]), "r"(b0), "r"(b1));
}

// ---------------------------------------------------------------------------
// Split-A 2xTF32 tensor-core GEMM:  C[M,N] = A[M,K] @ B[K,N] + bias[N]
// A is split a = hi + lo (both tf32) -> near-fp32 accuracy on the A side;
// only B's single tf32 rounding (~2.8e-4 RMS) remains.
//
// Tile 128x128x16. 256 threads = 8 warps in a 2x4 grid; warp tile 64x32
// (4 m-tiles x 4 n-tiles of m16n8k8). Double-buffered smem.
//
// Smem layouts (stride SB=136 floats per k-row):
//   AsH/AsL: [k][ m ^ (8*((k>>2)&3)) ]  -- XOR swizzle => conflict-free
//            scatter stores AND all 4 A-fragment load patterns.
//   Bs:      [k][ n ]                   -- pad-136 => conflict-free float4
//            stores and B-fragment loads (bank = 8*tq + gq + 8*nt).
// ---------------------------------------------------------------------------
#define SB     136
#define TILE_F (16 * SB)

__global__ __launch_bounds__(256)
void gemm_tf32_kernel(const float* __restrict__ A, const float* __restrict__ B,
                      const float* __restrict__ bias, float* __restrict__ C,
                      int M, int N, int K)
{
    extern __shared__ float smf[];
    float* AsH = smf;                  // [2][TILE_F]
    float* AsL = smf + 2 * TILE_F;     // [2][TILE_F]
    float* Bs  = smf + 4 * TILE_F;     // [2][TILE_F]

    const int tid  = threadIdx.x;
    const int lane = tid & 31;
    const int gq   = lane >> 2;        // 0..7
    const int tq   = lane & 3;         // 0..3
    const int w    = tid >> 5;
    const int mw   = (w >> 2) * 64;    // 0 | 64
    const int nw   = (w & 3) * 32;     // 0,32,64,96
    const int brow = blockIdx.y * 128;
    const int bcol = blockIdx.x * 128;

    float4 aReg[2], bReg[2];

    // Global loads -> regs (A: 128x16, B: 16x128; 2 float4 each per thread)
    auto gload = [&](int k0) {
        #pragma unroll
        for (int i = 0; i < 2; i++) {
            const int idx = tid + i * 256;
            aReg[i] = *reinterpret_cast<const float4*>(
                &A[(size_t)(brow + (idx >> 2)) * K + k0 + ((idx & 3) << 2)]);
            bReg[i] = *reinterpret_cast<const float4*>(
                &B[(size_t)(k0 + (idx >> 5)) * N + bcol + ((idx & 31) << 2)]);
        }
    };

    // Regs -> smem (with tf32 split/round + swizzle)
    auto sstore = [&](int buf) {
        float* ah = AsH + buf * TILE_F;
        float* al = AsL + buf * TILE_F;
        float* bs = Bs  + buf * TILE_F;
        #pragma unroll
        for (int i = 0; i < 2; i++) {
            const int idx = tid + i * 256;
            const int r = idx >> 2, kq = (idx & 3) << 2;
            #pragma unroll
            for (int j = 0; j < 4; j++) {
                const int k  = kq + j;
                const int ms = r ^ (((k >> 2) & 3) << 3);
                const float v  = (&aReg[i].x)[j];
                const float hi = f2tf32(v);
                ah[k * SB + ms] = hi;
                al[k * SB + ms] = f2tf32(v - hi);
            }
            const int kr = idx >> 5, n4 = (idx & 31) << 2;
            float4 t;
            t.x = f2tf32(bReg[i].x); t.y = f2tf32(bReg[i].y);
            t.z = f2tf32(bReg[i].z); t.w = f2tf32(bReg[i].w);
            *reinterpret_cast<float4*>(&bs[kr * SB + n4]) = t;
        }
    };

    float acc[4][4][4] = {};

    auto compute = [&](int buf) {
        const float* ah = AsH + buf * TILE_F;
        const float* al = AsL + buf * TILE_F;
        const float* bs = Bs  + buf * TILE_F;
        #pragma unroll
        for (int kk = 0; kk < 2; kk++) {
            uint32_t bf[4][2];
            #pragma unroll
            for (int nt = 0; nt < 4; nt++) {
                const float* bp = bs + (kk * 8 + tq) * SB + nw + nt * 8 + gq;
                bf[nt][0] = __float_as_uint(bp[0]);
                bf[nt][1] = __float_as_uint(bp[4 * SB]);
            }
            #pragma unroll
            for (int mt = 0; mt < 4; mt++) {
                const int m0  = mw + mt * 16;
                const int k0a = kk * 8 + tq;
                const int sw0 = kk * 16;          // 8*((k0a>>2)&3)
                const int sw1 = sw0 + 8;
                uint32_t af[4], ar[4];
                af[0] = __float_as_uint(ah[k0a * SB + ((m0 + gq) ^ sw0)]);
                af[1] = __float_as_uint(ah[k0a * SB + ((m0 + gq + 8) ^ sw0)]);
                af[2] = __float_as_uint(ah[(k0a + 4) * SB + ((m0 + gq) ^ sw1)]);
                af[3] = __float_as_uint(ah[(k0a + 4) * SB + ((m0 + gq + 8) ^ sw1)]);
                ar[0] = __float_as_uint(al[k0a * SB + ((m0 + gq) ^ sw0)]);
                ar[1] = __float_as_uint(al[k0a * SB + ((m0 + gq + 8) ^ sw0)]);
                ar[2] = __float_as_uint(al[(k0a + 4) * SB + ((m0 + gq) ^ sw1)]);
                ar[3] = __float_as_uint(al[(k0a + 4) * SB + ((m0 + gq + 8) ^ sw1)]);
                #pragma unroll
                for (int nt = 0; nt < 4; nt++) {
                    mma_tf32(acc[mt][nt], af, bf[nt][0], bf[nt][1]);
                    mma_tf32(acc[mt][nt], ar, bf[nt][0], bf[nt][1]);
                }
            }
        }
    };

    const int NIT = K >> 4;
    gload(0);
    sstore(0);
    __syncthreads();
    int buf = 0;
    #pragma unroll 1
    for (int it = 0; it < NIT; it++) {
        if (it + 1 < NIT) gload((it + 1) << 4);
        compute(buf);
        if (it + 1 < NIT) sstore(buf ^ 1);
        __syncthreads();
        buf ^= 1;
    }

    // Epilogue: + bias, float2 stores
    #pragma unroll
    for (int mt = 0; mt < 4; mt++) {
        #pragma unroll
        for (int nt = 0; nt < 4; nt++) {
            const int row = brow + mw + mt * 16 + gq;
            const int col = bcol + nw + nt * 8 + 2 * tq;
            const float2 bb = *reinterpret_cast<const float2*>(&bias[col]);
            float2 v0, v1;
            v0.x = acc[mt][nt][0] + bb.x; v0.y = acc[mt][nt][1] + bb.y;
            v1.x = acc[mt][nt][2] + bb.x; v1.y = acc[mt][nt][3] + bb.y;
            *reinterpret_cast<float2*>(&C[(size_t)row * N + col]) = v0;
            *reinterpret_cast<float2*>(&C[(size_t)(row + 8) * N + col]) = v1;
        }
    }
}

// ---------------------------------------------------------------------------
// Tensor-core flash attention (tf32 mma, fp32 softmax state) — unchanged
// from the passing round (220us, verified).
// ---------------------------------------------------------------------------
#define KST 76

__global__ __launch_bounds__(128, 2)
void attn_tc_kernel(const float* __restrict__ qkv, float* __restrict__ out)
{
    const int qb = gridDim.x - 1 - blockIdx.x;   // heavy blocks first
    const int h  = blockIdx.y;
    const int b  = blockIdx.z;

    extern __shared__ float sm[];
    float* Ks = sm;                 // [64][76]
    float* Vs = Ks + 64 * KST;      // [64][76]
    float* Ps = Vs + 64 * KST;      // [64][76]

    const int tid  = threadIdx.x;
    const int w    = tid >> 5;
    const int lane = tid & 31;
    const int gq   = lane >> 2;
    const int tq   = lane & 3;

    const size_t tok0 = (size_t)(b * SS + qb * 64);

    #pragma unroll
    for (int it = 0; it < 8; it++) {
        const int idx = tid + it * 128;
        const int r = idx >> 4, c4 = (idx & 15) << 2;
        const float4 v = *reinterpret_cast<const float4*>(
            qkv + (tok0 + r) * C3 + h * 192 + c4);
        float* d = Ps + r * KST + c4;
        d[0] = f2tf32(v.x); d[1] = f2tf32(v.y);
        d[2] = f2tf32(v.z); d[3] = f2tf32(v.w);
    }
    __syncthreads();

    uint32_t qf[8][4];
    #pragma unroll
    for (int k = 0; k < 8; k++) {
        const float* base = Ps + (w * 16) * KST + k * 8 + tq;
        qf[k][0] = __float_as_uint(base[gq * KST]);
        qf[k][1] = __float_as_uint(base[(gq + 8) * KST]);
        qf[k][2] = __float_as_uint(base[gq * KST + 4]);
        qf[k][3] = __float_as_uint(base[(gq + 8) * KST + 4]);
    }

    float m0 = -1e30f, m1 = -1e30f, l0 = 0.f, l1 = 0.f;
    float o[8][4];
    #pragma unroll
    for (int n = 0; n < 8; n++) { o[n][0]=o[n][1]=o[n][2]=o[n][3]=0.f; }

    const int rowA = w * 16 + gq;
    const int rowB = rowA + 8;

    for (int j = 0; j <= qb; j++) {
        __syncthreads();
        const size_t kt0 = (size_t)(b * SS + j * 64);
        #pragma unroll
        for (int it = 0; it < 8; it++) {
            const int idx = tid + it * 128;
            const int r = idx >> 4, c4 = (idx & 15) << 2;
            const float* src = qkv + (kt0 + r) * C3 + h * 192;
            const float4 kv = *reinterpret_cast<const float4*>(src + 64 + c4);
            float* dk = Ks + r * KST + c4;
            dk[0] = f2tf32(kv.x); dk[1] = f2tf32(kv.y);
            dk[2] = f2tf32(kv.z); dk[3] = f2tf32(kv.w);
            const float4 vv = *reinterpret_cast<const float4*>(src + 128 + c4);
            float* dv = Vs + r * KST + c4;
            dv[0] = f2tf32(vv.x); dv[1] = f2tf32(vv.y);
            dv[2] = f2tf32(vv.z); dv[3] = f2tf32(vv.w);
        }
        __syncthreads();

        const bool diag = (j == qb);
        const int  nmax = diag ? (2 * w + 1) : 7;

        float s[8][4];
        #pragma unroll
        for (int n = 0; n < 8; n++) { s[n][0]=s[n][1]=s[n][2]=s[n][3]=0.f; }
        for (int n = 0; n <= nmax; n++) {
            const float* kb = Ks + (n * 8 + gq) * KST + tq;
            #pragma unroll
            for (int k = 0; k < 8; k++) {
                const uint32_t b0 = __float_as_uint(kb[k * 8]);
                const uint32_t b1 = __float_as_uint(kb[k * 8 + 4]);
                mma_tf32(s[n], qf[k], b0, b1);
            }
        }

        float mx0 = -1e30f, mx1 = -1e30f;
        for (int n = 0; n <= nmax; n++) {
            s[n][0] *= 0.125f; s[n][1] *= 0.125f;
            s[n][2] *= 0.125f; s[n][3] *= 0.125f;
            if (diag) {
                const int col = n * 8 + 2 * tq;
                if (col     > rowA) s[n][0] = -1e30f;
                if (col + 1 > rowA) s[n][1] = -1e30f;
                if (col     > rowB) s[n][2] = -1e30f;
                if (col + 1 > rowB) s[n][3] = -1e30f;
            }
            mx0 = fmaxf(mx0, fmaxf(s[n][0], s[n][1]));
            mx1 = fmaxf(mx1, fmaxf(s[n][2], s[n][3]));
        }
        mx0 = fmaxf(mx0, __shfl_xor_sync(0xFFFFFFFFu, mx0, 1));
        mx0 = fmaxf(mx0, __shfl_xor_sync(0xFFFFFFFFu, mx0, 2));
        mx1 = fmaxf(mx1, __shfl_xor_sync(0xFFFFFFFFu, mx1, 1));
        mx1 = fmaxf(mx1, __shfl_xor_sync(0xFFFFFFFFu, mx1, 2));

        const float nm0 = fmaxf(m0, mx0), nm1 = fmaxf(m1, mx1);
        const float cf0 = __expf(m0 - nm0), cf1 = __expf(m1 - nm1);
        l0 *= cf0; l1 *= cf1;
        #pragma unroll
        for (int n = 0; n < 8; n++) {
            o[n][0] *= cf0; o[n][1] *= cf0;
            o[n][2] *= cf1; o[n][3] *= cf1;
        }

        float ps0 = 0.f, ps1 = 0.f;
        for (int n = 0; n <= nmax; n++) {
            const float p0 = __expf(s[n][0] - nm0);
            const float p1 = __expf(s[n][1] - nm0);
            const float p2 = __expf(s[n][2] - nm1);
            const float p3 = __expf(s[n][3] - nm1);
            ps0 += p0 + p1; ps1 += p2 + p3;
            float2 lo; lo.x = f2tf32(p0); lo.y = f2tf32(p1);
            float2 hi; hi.x = f2tf32(p2); hi.y = f2tf32(p3);
            *reinterpret_cast<float2*>(Ps + rowA * KST + n * 8 + 2 * tq) = lo;
            *reinterpret_cast<float2*>(Ps + rowB * KST + n * 8 + 2 * tq) = hi;
        }
        ps0 += __shfl_xor_sync(0xFFFFFFFFu, ps0, 1);
        ps0 += __shfl_xor_sync(0xFFFFFFFFu, ps0, 2);
        ps1 += __shfl_xor_sync(0xFFFFFFFFu, ps1, 1);
        ps1 += __shfl_xor_sync(0xFFFFFFFFu, ps1, 2);
        l0 += ps0; l1 += ps1; m0 = nm0; m1 = nm1;
        __syncwarp();

        for (int k = 0; k <= nmax; k++) {
            const float* pb = Ps + (w * 16) * KST + k * 8 + tq;
            uint32_t pa[4];
            pa[0] = __float_as_uint(pb[gq * KST]);
            pa[1] = __float_as_uint(pb[(gq + 8) * KST]);
            pa[2] = __float_as_uint(pb[gq * KST + 4]);
            pa[3] = __float_as_uint(pb[(gq + 8) * KST + 4]);
            const float* vb = Vs + (k * 8 + tq) * KST + gq;
            #pragma unroll
            for (int n = 0; n < 8; n++) {
                const uint32_t b0 = __float_as_uint(vb[n * 8]);
                const uint32_t b1 = __float_as_uint(vb[4 * KST + n * 8]);
                mma_tf32(o[n], pa, b0, b1);
            }
        }
    }

    const float i0 = 1.f / l0, i1 = 1.f / l1;
    float* dstA = out + (tok0 + rowA) * EE + h * HD;
    float* dstB = out + (tok0 + rowB) * EE + h * HD;
    #pragma unroll
    for (int n = 0; n < 8; n++) {
        float2 a; a.x = o[n][0] * i0; a.y = o[n][1] * i0;
        float2 c; c.x = o[n][2] * i1; c.y = o[n][3] * i1;
        *reinterpret_cast<float2*>(dstA + n * 8 + 2 * tq) = a;
        *reinterpret_cast<float2*>(dstB + n * 8 + 2 * tq) = c;
    }
}

// ---------------------------------------------------------------------------
extern "C" void kernel_launch(void* const* d_in, const int* in_sizes, int n_in,
                              void* d_out, int out_size)
{
    const float* x  = (const float*)d_in[0];  // hidden_states [2,2048,1024]
    const float* Wa = (const float*)d_in[1];  // W_attn [1024,3072]
    const float* ba = (const float*)d_in[2];  // b_attn [3072]
    const float* Wp = (const float*)d_in[3];  // W_proj [1024,1024]
    const float* bp = (const float*)d_in[4];  // b_proj [1024]
    float* out = (float*)d_out;               // [2,2048,1024]

    float *qkv, *att;
    cudaGetSymbolAddress((void**)&qkv, g_qkv);
    cudaGetSymbolAddress((void**)&att, g_att);

    const int gemm_smem = 6 * TILE_F * sizeof(float);   // 52224 B
    cudaFuncSetAttribute(gemm_tf32_kernel,
                         cudaFuncAttributeMaxDynamicSharedMemorySize, gemm_smem);

    // 1) QKV projection (split-A 2xTF32 tensor cores)
    gemm_tf32_kernel<<<dim3(C3 / 128, MTOK / 128), 256, gemm_smem>>>(
        x, Wa, ba, qkv, MTOK, C3, EE);

    // 2) Tensor-core fused causal attention
    const size_t shmem = (size_t)(3 * 64 * KST) * sizeof(float);  // 58368 B
    cudaFuncSetAttribute(attn_tc_kernel, cudaFuncAttributeMaxDynamicSharedMemorySize, (int)shmem);
    attn_tc_kernel<<<dim3(SS / 64, HH, BB), 128, shmem>>>(qkv, att);

    // 3) Output projection (split-A 2xTF32 tensor cores)
    gemm_tf32_kernel<<<dim3(EE / 128, MTOK / 128), 256, gemm_smem>>>(
        att, Wp, bp, out, MTOK, EE, EE);
}

// round 7
// speedup vs baseline: 4.2082x; 1.1836x over previous
#include <cuda_runtime.h>
#include <cuda_bf16.h>
#include <math.h>
#include <stdint.h>

// Problem constants
#define BB   2
#define SS   2048
#define EE   1024
#define HH   16
#define HD   64
#define C3   3072          // 3*E
#define MTOK (BB*SS)       // 4096 tokens

// Scratch (static device globals — allocation-guard safe)
__device__ float g_qkv[(size_t)MTOK * C3];   // [4096, 3072] interleaved per head [q|k|v]
__device__ float g_att[(size_t)MTOK * EE];   // [4096, 1024] merged-head attention output

// ---------------------------------------------------------------------------
// tf32 helpers
// ---------------------------------------------------------------------------
__device__ __forceinline__ float f2tf32(float f) {
    uint32_t u;
    asm("cvt.rna.tf32.f32 %0, %1;" : "=r"(u) : "f"(f));
    return __uint_as_float(u);
}

__device__ __forceinline__ void mma_tf32(float* d, const uint32_t* a,
                                         uint32_t b0, uint32_t b1) {
    asm volatile(
        "mma.sync.aligned.m16n8k8.row.col.f32.tf32.tf32.f32 "
        "{%0,%1,%2,%3}, {%4,%5,%6,%7}, {%8,%9}, {%0,%1,%2,%3};"
        : "+f"(d[0]), "+f"(d[1]), "+f"(d[2]), "+f"(d[3])
        : "r"(a[0]), "r"(a[1]), "r"(a[2]), "r"(a[3]), "r"(b0), "r"(b1));
}

__device__ __forceinline__ void ldsm_x4(uint32_t* r, uint32_t addr) {
    asm volatile("ldmatrix.sync.aligned.m8n8.x4.shared.b16 {%0,%1,%2,%3}, [%4];"
        : "=r"(r[0]), "=r"(r[1]), "=r"(r[2]), "=r"(r[3]) : "r"(addr));
}

// ---------------------------------------------------------------------------
// Split-A 2xTF32 tensor-core GEMM:  C[M,N] = A[M,K] @ B[K,N] + bias[N]
// A split a = hi + lo (both tf32): A-side near-fp32; only B's tf32 rounding
// (~2.8e-4 RMS) remains.
//
// Tile 128x128x16, 256 threads = 8 warps (2x4), warp tile 64x32.
// Double-buffered smem. 2 CTAs/SM (regs capped at 128).
//
// Smem:
//   AsH/AsL: row-major [m][k], row stride AST=20 floats. float4 stores;
//            A-fragments via ldmatrix.x4 (8-row phases hit distinct banks:
//            20m mod 32 = {0,20,8,28,16,4,24,12}).
//   Bs:      [k][n], stride 136 -> conflict-free float4 stores and B-frag
//            LDS (bank = 8*tq + gq + 8*nt, distinct per warp).
// ---------------------------------------------------------------------------
#define AST    20
#define A_TILE (128 * AST)     // 2560 floats
#define BST    136
#define B_TILE (16 * BST)      // 2176 floats

__global__ __launch_bounds__(256, 2)
void gemm_tf32_kernel(const float* __restrict__ A, const float* __restrict__ B,
                      const float* __restrict__ bias, float* __restrict__ C,
                      int M, int N, int K)
{
    extern __shared__ float smf[];
    float* AsH = smf;                    // [2][A_TILE]
    float* AsL = smf + 2 * A_TILE;       // [2][A_TILE]
    float* Bs  = smf + 4 * A_TILE;       // [2][B_TILE]

    const int tid  = threadIdx.x;
    const int lane = tid & 31;
    const int gq   = lane >> 2;        // 0..7
    const int tq   = lane & 3;         // 0..3
    const int w    = tid >> 5;
    const int mw   = (w >> 2) * 64;    // 0 | 64
    const int nw   = (w & 3) * 32;     // 0,32,64,96
    const int brow = blockIdx.y * 128;
    const int bcol = blockIdx.x * 128;

    // Per-thread ldmatrix source offset within an A tile (bytes):
    // matrix id = lane>>3: 0:[m0:8,k0:4] 1:[m8:16,k0:4] 2:[m0:8,k4:8] 3:[m8:16,k4:8]
    const int lm_m = mw + ((lane >> 3) & 1) * 8 + (lane & 7);
    const int lm_k = (lane >> 4) * 4;
    const uint32_t sbase = (uint32_t)__cvta_generic_to_shared(smf);
    const uint32_t lm_off = (uint32_t)((lm_m * AST + lm_k) * 4);

    float4 aReg[2], bReg[2];

    auto gload = [&](int k0) {
        #pragma unroll
        for (int i = 0; i < 2; i++) {
            const int idx = tid + i * 256;
            aReg[i] = *reinterpret_cast<const float4*>(
                &A[(size_t)(brow + (idx >> 2)) * K + k0 + ((idx & 3) << 2)]);
            bReg[i] = *reinterpret_cast<const float4*>(
                &B[(size_t)(k0 + (idx >> 5)) * N + bcol + ((idx & 31) << 2)]);
        }
    };

    auto sstore = [&](int buf) {
        float* ah = AsH + buf * A_TILE;
        float* al = AsL + buf * A_TILE;
        float* bs = Bs  + buf * B_TILE;
        #pragma unroll
        for (int i = 0; i < 2; i++) {
            const int idx = tid + i * 256;
            const int r = idx >> 2, kq = (idx & 3) << 2;
            float4 hi, lo;
            hi.x = f2tf32(aReg[i].x); lo.x = f2tf32(aReg[i].x - hi.x);
            hi.y = f2tf32(aReg[i].y); lo.y = f2tf32(aReg[i].y - hi.y);
            hi.z = f2tf32(aReg[i].z); lo.z = f2tf32(aReg[i].z - hi.z);
            hi.w = f2tf32(aReg[i].w); lo.w = f2tf32(aReg[i].w - hi.w);
            *reinterpret_cast<float4*>(&ah[r * AST + kq]) = hi;
            *reinterpret_cast<float4*>(&al[r * AST + kq]) = lo;
            const int kr = idx >> 5, n4 = (idx & 31) << 2;
            float4 t;
            t.x = f2tf32(bReg[i].x); t.y = f2tf32(bReg[i].y);
            t.z = f2tf32(bReg[i].z); t.w = f2tf32(bReg[i].w);
            *reinterpret_cast<float4*>(&bs[kr * BST + n4]) = t;
        }
    };

    float acc[4][4][4] = {};

    auto compute = [&](int buf) {
        const uint32_t ah_b = sbase + (uint32_t)(buf * A_TILE * 4) + lm_off;
        const uint32_t al_b = ah_b + (uint32_t)(2 * A_TILE * 4);
        const float*   bs   = Bs + buf * B_TILE;
        #pragma unroll
        for (int kk = 0; kk < 2; kk++) {
            uint32_t bf[4][2];
            #pragma unroll
            for (int nt = 0; nt < 4; nt++) {
                const float* bp = bs + (kk * 8 + tq) * BST + nw + nt * 8 + gq;
                bf[nt][0] = __float_as_uint(bp[0]);
                bf[nt][1] = __float_as_uint(bp[4 * BST]);
            }
            #pragma unroll
            for (int mt = 0; mt < 4; mt++) {
                const uint32_t toff = (uint32_t)((mt * 16 * AST + kk * 8) * 4);
                uint32_t af[4], ar[4];
                ldsm_x4(af, ah_b + toff);
                ldsm_x4(ar, al_b + toff);
                #pragma unroll
                for (int nt = 0; nt < 4; nt++) {
                    mma_tf32(acc[mt][nt], af, bf[nt][0], bf[nt][1]);
                    mma_tf32(acc[mt][nt], ar, bf[nt][0], bf[nt][1]);
                }
            }
        }
    };

    const int NIT = K >> 4;
    gload(0);
    sstore(0);
    __syncthreads();
    int buf = 0;
    #pragma unroll 1
    for (int it = 0; it < NIT; it++) {
        if (it + 1 < NIT) gload((it + 1) << 4);
        compute(buf);
        if (it + 1 < NIT) sstore(buf ^ 1);
        __syncthreads();
        buf ^= 1;
    }

    // Epilogue: + bias, float2 stores
    #pragma unroll
    for (int mt = 0; mt < 4; mt++) {
        #pragma unroll
        for (int nt = 0; nt < 4; nt++) {
            const int row = brow + mw + mt * 16 + gq;
            const int col = bcol + nw + nt * 8 + 2 * tq;
            const float2 bb = *reinterpret_cast<const float2*>(&bias[col]);
            float2 v0, v1;
            v0.x = acc[mt][nt][0] + bb.x; v0.y = acc[mt][nt][1] + bb.y;
            v1.x = acc[mt][nt][2] + bb.x; v1.y = acc[mt][nt][3] + bb.y;
            *reinterpret_cast<float2*>(&C[(size_t)row * N + col]) = v0;
            *reinterpret_cast<float2*>(&C[(size_t)(row + 8) * N + col]) = v1;
        }
    }
}

// ---------------------------------------------------------------------------
// Tensor-core flash attention (tf32 mma, fp32 softmax state) — unchanged,
// verified (~220us, rel_err 2.8e-4 contribution).
// ---------------------------------------------------------------------------
#define KST 76

__global__ __launch_bounds__(128, 2)
void attn_tc_kernel(const float* __restrict__ qkv, float* __restrict__ out)
{
    const int qb = gridDim.x - 1 - blockIdx.x;   // heavy blocks first
    const int h  = blockIdx.y;
    const int b  = blockIdx.z;

    extern __shared__ float sm[];
    float* Ks = sm;                 // [64][76]
    float* Vs = Ks + 64 * KST;      // [64][76]
    float* Ps = Vs + 64 * KST;      // [64][76]

    const int tid  = threadIdx.x;
    const int w    = tid >> 5;
    const int lane = tid & 31;
    const int gq   = lane >> 2;
    const int tq   = lane & 3;

    const size_t tok0 = (size_t)(b * SS + qb * 64);

    #pragma unroll
    for (int it = 0; it < 8; it++) {
        const int idx = tid + it * 128;
        const int r = idx >> 4, c4 = (idx & 15) << 2;
        const float4 v = *reinterpret_cast<const float4*>(
            qkv + (tok0 + r) * C3 + h * 192 + c4);
        float* d = Ps + r * KST + c4;
        d[0] = f2tf32(v.x); d[1] = f2tf32(v.y);
        d[2] = f2tf32(v.z); d[3] = f2tf32(v.w);
    }
    __syncthreads();

    uint32_t qf[8][4];
    #pragma unroll
    for (int k = 0; k < 8; k++) {
        const float* base = Ps + (w * 16) * KST + k * 8 + tq;
        qf[k][0] = __float_as_uint(base[gq * KST]);
        qf[k][1] = __float_as_uint(base[(gq + 8) * KST]);
        qf[k][2] = __float_as_uint(base[gq * KST + 4]);
        qf[k][3] = __float_as_uint(base[(gq + 8) * KST + 4]);
    }

    float m0 = -1e30f, m1 = -1e30f, l0 = 0.f, l1 = 0.f;
    float o[8][4];
    #pragma unroll
    for (int n = 0; n < 8; n++) { o[n][0]=o[n][1]=o[n][2]=o[n][3]=0.f; }

    const int rowA = w * 16 + gq;
    const int rowB = rowA + 8;

    for (int j = 0; j <= qb; j++) {
        __syncthreads();
        const size_t kt0 = (size_t)(b * SS + j * 64);
        #pragma unroll
        for (int it = 0; it < 8; it++) {
            const int idx = tid + it * 128;
            const int r = idx >> 4, c4 = (idx & 15) << 2;
            const float* src = qkv + (kt0 + r) * C3 + h * 192;
            const float4 kv = *reinterpret_cast<const float4*>(src + 64 + c4);
            float* dk = Ks + r * KST + c4;
            dk[0] = f2tf32(kv.x); dk[1] = f2tf32(kv.y);
            dk[2] = f2tf32(kv.z); dk[3] = f2tf32(kv.w);
            const float4 vv = *reinterpret_cast<const float4*>(src + 128 + c4);
            float* dv = Vs + r * KST + c4;
            dv[0] = f2tf32(vv.x); dv[1] = f2tf32(vv.y);
            dv[2] = f2tf32(vv.z); dv[3] = f2tf32(vv.w);
        }
        __syncthreads();

        const bool diag = (j == qb);
        const int  nmax = diag ? (2 * w + 1) : 7;

        float s[8][4];
        #pragma unroll
        for (int n = 0; n < 8; n++) { s[n][0]=s[n][1]=s[n][2]=s[n][3]=0.f; }
        for (int n = 0; n <= nmax; n++) {
            const float* kb = Ks + (n * 8 + gq) * KST + tq;
            #pragma unroll
            for (int k = 0; k < 8; k++) {
                const uint32_t b0 = __float_as_uint(kb[k * 8]);
                const uint32_t b1 = __float_as_uint(kb[k * 8 + 4]);
                mma_tf32(s[n], qf[k], b0, b1);
            }
        }

        float mx0 = -1e30f, mx1 = -1e30f;
        for (int n = 0; n <= nmax; n++) {
            s[n][0] *= 0.125f; s[n][1] *= 0.125f;
            s[n][2] *= 0.125f; s[n][3] *= 0.125f;
            if (diag) {
                const int col = n * 8 + 2 * tq;
                if (col     > rowA) s[n][0] = -1e30f;
                if (col + 1 > rowA) s[n][1] = -1e30f;
                if (col     > rowB) s[n][2] = -1e30f;
                if (col + 1 > rowB) s[n][3] = -1e30f;
            }
            mx0 = fmaxf(mx0, fmaxf(s[n][0], s[n][1]));
            mx1 = fmaxf(mx1, fmaxf(s[n][2], s[n][3]));
        }
        mx0 = fmaxf(mx0, __shfl_xor_sync(0xFFFFFFFFu, mx0, 1));
        mx0 = fmaxf(mx0, __shfl_xor_sync(0xFFFFFFFFu, mx0, 2));
        mx1 = fmaxf(mx1, __shfl_xor_sync(0xFFFFFFFFu, mx1, 1));
        mx1 = fmaxf(mx1, __shfl_xor_sync(0xFFFFFFFFu, mx1, 2));

        const float nm0 = fmaxf(m0, mx0), nm1 = fmaxf(m1, mx1);
        const float cf0 = __expf(m0 - nm0), cf1 = __expf(m1 - nm1);
        l0 *= cf0; l1 *= cf1;
        #pragma unroll
        for (int n = 0; n < 8; n++) {
            o[n][0] *= cf0; o[n][1] *= cf0;
            o[n][2] *= cf1; o[n][3] *= cf1;
        }

        float ps0 = 0.f, ps1 = 0.f;
        for (int n = 0; n <= nmax; n++) {
            const float p0 = __expf(s[n][0] - nm0);
            const float p1 = __expf(s[n][1] - nm0);
            const float p2 = __expf(s[n][2] - nm1);
            const float p3 = __expf(s[n][3] - nm1);
            ps0 += p0 + p1; ps1 += p2 + p3;
            float2 lo; lo.x = f2tf32(p0); lo.y = f2tf32(p1);
            float2 hi; hi.x = f2tf32(p2); hi.y = f2tf32(p3);
            *reinterpret_cast<float2*>(Ps + rowA * KST + n * 8 + 2 * tq) = lo;
            *reinterpret_cast<float2*>(Ps + rowB * KST + n * 8 + 2 * tq) = hi;
        }
        ps0 += __shfl_xor_sync(0xFFFFFFFFu, ps0, 1);
        ps0 += __shfl_xor_sync(0xFFFFFFFFu, ps0, 2);
        ps1 += __shfl_xor_sync(0xFFFFFFFFu, ps1, 1);
        ps1 += __shfl_xor_sync(0xFFFFFFFFu, ps1, 2);
        l0 += ps0; l1 += ps1; m0 = nm0; m1 = nm1;
        __syncwarp();

        for (int k = 0; k <= nmax; k++) {
            const float* pb = Ps + (w * 16) * KST + k * 8 + tq;
            uint32_t pa[4];
            pa[0] = __float_as_uint(pb[gq * KST]);
            pa[1] = __float_as_uint(pb[(gq + 8) * KST]);
            pa[2] = __float_as_uint(pb[gq * KST + 4]);
            pa[3] = __float_as_uint(pb[(gq + 8) * KST + 4]);
            const float* vb = Vs + (k * 8 + tq) * KST + gq;
            #pragma unroll
            for (int n = 0; n < 8; n++) {
                const uint32_t b0 = __float_as_uint(vb[n * 8]);
                const uint32_t b1 = __float_as_uint(vb[4 * KST + n * 8]);
                mma_tf32(o[n], pa, b0, b1);
            }
        }
    }

    const float i0 = 1.f / l0, i1 = 1.f / l1;
    float* dstA = out + (tok0 + rowA) * EE + h * HD;
    float* dstB = out + (tok0 + rowB) * EE + h * HD;
    #pragma unroll
    for (int n = 0; n < 8; n++) {
        float2 a; a.x = o[n][0] * i0; a.y = o[n][1] * i0;
        float2 c; c.x = o[n][2] * i1; c.y = o[n][3] * i1;
        *reinterpret_cast<float2*>(dstA + n * 8 + 2 * tq) = a;
        *reinterpret_cast<float2*>(dstB + n * 8 + 2 * tq) = c;
    }
}

// ---------------------------------------------------------------------------
extern "C" void kernel_launch(void* const* d_in, const int* in_sizes, int n_in,
                              void* d_out, int out_size)
{
    const float* x  = (const float*)d_in[0];  // hidden_states [2,2048,1024]
    const float* Wa = (const float*)d_in[1];  // W_attn [1024,3072]
    const float* ba = (const float*)d_in[2];  // b_attn [3072]
    const float* Wp = (const float*)d_in[3];  // W_proj [1024,1024]
    const float* bp = (const float*)d_in[4];  // b_proj [1024]
    float* out = (float*)d_out;               // [2,2048,1024]

    float *qkv, *att;
    cudaGetSymbolAddress((void**)&qkv, g_qkv);
    cudaGetSymbolAddress((void**)&att, g_att);

    const int gemm_smem = (4 * A_TILE + 2 * B_TILE) * sizeof(float);  // 58368 B
    cudaFuncSetAttribute(gemm_tf32_kernel,
                         cudaFuncAttributeMaxDynamicSharedMemorySize, gemm_smem);

    // 1) QKV projection (split-A 2xTF32 tensor cores, ldmatrix A-frags)
    gemm_tf32_kernel<<<dim3(C3 / 128, MTOK / 128), 256, gemm_smem>>>(
        x, Wa, ba, qkv, MTOK, C3, EE);

    // 2) Tensor-core fused causal attention
    const size_t shmem = (size_t)(3 * 64 * KST) * sizeof(float);  // 58368 B
    cudaFuncSetAttribute(attn_tc_kernel, cudaFuncAttributeMaxDynamicSharedMemorySize, (int)shmem);
    attn_tc_kernel<<<dim3(SS / 64, HH, BB), 128, shmem>>>(qkv, att);

    // 3) Output projection (split-A 2xTF32 tensor cores, ldmatrix A-frags)
    gemm_tf32_kernel<<<dim3(EE / 128, MTOK / 128), 256, gemm_smem>>>(
        att, Wp, bp, out, MTOK, EE, EE);
}

// round 8
// speedup vs baseline: 5.4873x; 1.3040x over previous
#include <cuda_runtime.h>
#include <cuda_bf16.h>
#include <math.h>
#include <stdint.h>

// Problem constants
#define BB   2
#define SS   2048
#define EE   1024
#define HH   16
#define HD   64
#define C3   3072          // 3*E
#define MTOK (BB*SS)       // 4096 tokens

// Scratch (static device globals — allocation-guard safe)
__device__ float g_qkv[(size_t)MTOK * C3];   // [4096, 3072] interleaved per head [q|k|v]
__device__ float g_att[(size_t)MTOK * EE];   // [4096, 1024] merged-head attention output

// ---------------------------------------------------------------------------
// tf32 helpers
// ---------------------------------------------------------------------------
__device__ __forceinline__ float f2tf32(float f) {
    uint32_t u;
    asm("cvt.rna.tf32.f32 %0, %1;" : "=r"(u) : "f"(f));
    return __uint_as_float(u);
}

__device__ __forceinline__ void mma_tf32(float* d, const uint32_t* a,
                                         uint32_t b0, uint32_t b1) {
    asm volatile(
        "mma.sync.aligned.m16n8k8.row.col.f32.tf32.tf32.f32 "
        "{%0,%1,%2,%3}, {%4,%5,%6,%7}, {%8,%9}, {%0,%1,%2,%3};"
        : "+f"(d[0]), "+f"(d[1]), "+f"(d[2]), "+f"(d[3])
        : "r"(a[0]), "r"(a[1]), "r"(a[2]), "r"(a[3]), "r"(b0), "r"(b1));
}

__device__ __forceinline__ void ldsm_x4(uint32_t* r, uint32_t addr) {
    asm volatile("ldmatrix.sync.aligned.m8n8.x4.shared.b16 {%0,%1,%2,%3}, [%4];"
        : "=r"(r[0]), "=r"(r[1]), "=r"(r[2]), "=r"(r[3]) : "r"(addr));
}

// ---------------------------------------------------------------------------
// TF32 tensor-core GEMM:  C[M,N] = A[M,K] @ B[K,N] + bias[N]
// Single-pass tf32 (round-to-nearest on both operands): ~3.1e-4 RMS per GEMM,
// fits the 1e-3 budget with 2x margin (measured R5/R6 decomposition).
//
// Tile 128x128x16, 256 threads = 8 warps (2x4), warp tile 64x32.
// Double-buffered smem, 2 CTAs/SM.
//
// Smem:
//   As: row-major [m][k], row stride AST=20 floats. float4 stores;
//       A-fragments via ldmatrix.x4 (8-row phases hit distinct banks:
//       20m mod 32 = {0,20,8,28,16,4,24,12}).
//   Bs: [k][n], stride 136 -> conflict-free float4 stores and B-frag LDS.
// ---------------------------------------------------------------------------
#define AST    20
#define A_TILE (128 * AST)     // 2560 floats
#define BST    136
#define B_TILE (16 * BST)      // 2176 floats

__global__ __launch_bounds__(256, 2)
void gemm_tf32_kernel(const float* __restrict__ A, const float* __restrict__ B,
                      const float* __restrict__ bias, float* __restrict__ C,
                      int M, int N, int K)
{
    extern __shared__ float smf[];
    float* As = smf;                    // [2][A_TILE]
    float* Bs = smf + 2 * A_TILE;       // [2][B_TILE]

    const int tid  = threadIdx.x;
    const int lane = tid & 31;
    const int gq   = lane >> 2;        // 0..7
    const int tq   = lane & 3;         // 0..3
    const int w    = tid >> 5;
    const int mw   = (w >> 2) * 64;    // 0 | 64
    const int nw   = (w & 3) * 32;     // 0,32,64,96
    const int brow = blockIdx.y * 128;
    const int bcol = blockIdx.x * 128;

    // Per-thread ldmatrix source offset within an A tile (bytes):
    // matrix id = lane>>3: 0:[m0:8,k0:4] 1:[m8:16,k0:4] 2:[m0:8,k4:8] 3:[m8:16,k4:8]
    const int lm_m = mw + ((lane >> 3) & 1) * 8 + (lane & 7);
    const int lm_k = (lane >> 4) * 4;
    const uint32_t sbase = (uint32_t)__cvta_generic_to_shared(smf);
    const uint32_t lm_off = (uint32_t)((lm_m * AST + lm_k) * 4);

    float4 aReg[2], bReg[2];

    auto gload = [&](int k0) {
        #pragma unroll
        for (int i = 0; i < 2; i++) {
            const int idx = tid + i * 256;
            aReg[i] = *reinterpret_cast<const float4*>(
                &A[(size_t)(brow + (idx >> 2)) * K + k0 + ((idx & 3) << 2)]);
            bReg[i] = *reinterpret_cast<const float4*>(
                &B[(size_t)(k0 + (idx >> 5)) * N + bcol + ((idx & 31) << 2)]);
        }
    };

    auto sstore = [&](int buf) {
        float* as = As + buf * A_TILE;
        float* bs = Bs + buf * B_TILE;
        #pragma unroll
        for (int i = 0; i < 2; i++) {
            const int idx = tid + i * 256;
            const int r = idx >> 2, kq = (idx & 3) << 2;
            float4 av;
            av.x = f2tf32(aReg[i].x); av.y = f2tf32(aReg[i].y);
            av.z = f2tf32(aReg[i].z); av.w = f2tf32(aReg[i].w);
            *reinterpret_cast<float4*>(&as[r * AST + kq]) = av;
            const int kr = idx >> 5, n4 = (idx & 31) << 2;
            float4 t;
            t.x = f2tf32(bReg[i].x); t.y = f2tf32(bReg[i].y);
            t.z = f2tf32(bReg[i].z); t.w = f2tf32(bReg[i].w);
            *reinterpret_cast<float4*>(&bs[kr * BST + n4]) = t;
        }
    };

    float acc[4][4][4] = {};

    auto compute = [&](int buf) {
        const uint32_t as_b = sbase + (uint32_t)(buf * A_TILE * 4) + lm_off;
        const float*   bs   = Bs + buf * B_TILE;
        #pragma unroll
        for (int kk = 0; kk < 2; kk++) {
            uint32_t bf[4][2];
            #pragma unroll
            for (int nt = 0; nt < 4; nt++) {
                const float* bp = bs + (kk * 8 + tq) * BST + nw + nt * 8 + gq;
                bf[nt][0] = __float_as_uint(bp[0]);
                bf[nt][1] = __float_as_uint(bp[4 * BST]);
            }
            #pragma unroll
            for (int mt = 0; mt < 4; mt++) {
                uint32_t af[4];
                ldsm_x4(af, as_b + (uint32_t)((mt * 16 * AST + kk * 8) * 4));
                #pragma unroll
                for (int nt = 0; nt < 4; nt++)
                    mma_tf32(acc[mt][nt], af, bf[nt][0], bf[nt][1]);
            }
        }
    };

    const int NIT = K >> 4;
    gload(0);
    sstore(0);
    __syncthreads();
    int buf = 0;
    #pragma unroll 1
    for (int it = 0; it < NIT; it++) {
        if (it + 1 < NIT) gload((it + 1) << 4);
        compute(buf);
        if (it + 1 < NIT) sstore(buf ^ 1);
        __syncthreads();
        buf ^= 1;
    }

    // Epilogue: + bias, float2 stores
    #pragma unroll
    for (int mt = 0; mt < 4; mt++) {
        #pragma unroll
        for (int nt = 0; nt < 4; nt++) {
            const int row = brow + mw + mt * 16 + gq;
            const int col = bcol + nw + nt * 8 + 2 * tq;
            const float2 bb = *reinterpret_cast<const float2*>(&bias[col]);
            float2 v0, v1;
            v0.x = acc[mt][nt][0] + bb.x; v0.y = acc[mt][nt][1] + bb.y;
            v1.x = acc[mt][nt][2] + bb.x; v1.y = acc[mt][nt][3] + bb.y;
            *reinterpret_cast<float2*>(&C[(size_t)row * N + col]) = v0;
            *reinterpret_cast<float2*>(&C[(size_t)(row + 8) * N + col]) = v1;
        }
    }
}

// ---------------------------------------------------------------------------
// Tensor-core flash attention (tf32 mma, fp32 softmax state).
// Occupancy raised to 3 CTAs/SM (3 x 58KB smem = 175KB fits; regs <= 170).
// ---------------------------------------------------------------------------
#define KST 76

__global__ __launch_bounds__(128, 3)
void attn_tc_kernel(const float* __restrict__ qkv, float* __restrict__ out)
{
    const int qb = gridDim.x - 1 - blockIdx.x;   // heavy blocks first
    const int h  = blockIdx.y;
    const int b  = blockIdx.z;

    extern __shared__ float sm[];
    float* Ks = sm;                 // [64][76]
    float* Vs = Ks + 64 * KST;      // [64][76]
    float* Ps = Vs + 64 * KST;      // [64][76]

    const int tid  = threadIdx.x;
    const int w    = tid >> 5;
    const int lane = tid & 31;
    const int gq   = lane >> 2;
    const int tq   = lane & 3;

    const size_t tok0 = (size_t)(b * SS + qb * 64);

    #pragma unroll
    for (int it = 0; it < 8; it++) {
        const int idx = tid + it * 128;
        const int r = idx >> 4, c4 = (idx & 15) << 2;
        const float4 v = *reinterpret_cast<const float4*>(
            qkv + (tok0 + r) * C3 + h * 192 + c4);
        float* d = Ps + r * KST + c4;
        d[0] = f2tf32(v.x); d[1] = f2tf32(v.y);
        d[2] = f2tf32(v.z); d[3] = f2tf32(v.w);
    }
    __syncthreads();

    uint32_t qf[8][4];
    #pragma unroll
    for (int k = 0; k < 8; k++) {
        const float* base = Ps + (w * 16) * KST + k * 8 + tq;
        qf[k][0] = __float_as_uint(base[gq * KST]);
        qf[k][1] = __float_as_uint(base[(gq + 8) * KST]);
        qf[k][2] = __float_as_uint(base[gq * KST + 4]);
        qf[k][3] = __float_as_uint(base[(gq + 8) * KST + 4]);
    }

    float m0 = -1e30f, m1 = -1e30f, l0 = 0.f, l1 = 0.f;
    float o[8][4];
    #pragma unroll
    for (int n = 0; n < 8; n++) { o[n][0]=o[n][1]=o[n][2]=o[n][3]=0.f; }

    const int rowA = w * 16 + gq;
    const int rowB = rowA + 8;

    for (int j = 0; j <= qb; j++) {
        __syncthreads();
        const size_t kt0 = (size_t)(b * SS + j * 64);
        #pragma unroll
        for (int it = 0; it < 8; it++) {
            const int idx = tid + it * 128;
            const int r = idx >> 4, c4 = (idx & 15) << 2;
            const float* src = qkv + (kt0 + r) * C3 + h * 192;
            const float4 kv = *reinterpret_cast<const float4*>(src + 64 + c4);
            float* dk = Ks + r * KST + c4;
            dk[0] = f2tf32(kv.x); dk[1] = f2tf32(kv.y);
            dk[2] = f2tf32(kv.z); dk[3] = f2tf32(kv.w);
            const float4 vv = *reinterpret_cast<const float4*>(src + 128 + c4);
            float* dv = Vs + r * KST + c4;
            dv[0] = f2tf32(vv.x); dv[1] = f2tf32(vv.y);
            dv[2] = f2tf32(vv.z); dv[3] = f2tf32(vv.w);
        }
        __syncthreads();

        const bool diag = (j == qb);
        const int  nmax = diag ? (2 * w + 1) : 7;

        float s[8][4];
        #pragma unroll
        for (int n = 0; n < 8; n++) { s[n][0]=s[n][1]=s[n][2]=s[n][3]=0.f; }
        for (int n = 0; n <= nmax; n++) {
            const float* kb = Ks + (n * 8 + gq) * KST + tq;
            #pragma unroll
            for (int k = 0; k < 8; k++) {
                const uint32_t b0 = __float_as_uint(kb[k * 8]);
                const uint32_t b1 = __float_as_uint(kb[k * 8 + 4]);
                mma_tf32(s[n], qf[k], b0, b1);
            }
        }

        float mx0 = -1e30f, mx1 = -1e30f;
        for (int n = 0; n <= nmax; n++) {
            s[n][0] *= 0.125f; s[n][1] *= 0.125f;
            s[n][2] *= 0.125f; s[n][3] *= 0.125f;
            if (diag) {
                const int col = n * 8 + 2 * tq;
                if (col     > rowA) s[n][0] = -1e30f;
                if (col + 1 > rowA) s[n][1] = -1e30f;
                if (col     > rowB) s[n][2] = -1e30f;
                if (col + 1 > rowB) s[n][3] = -1e30f;
            }
            mx0 = fmaxf(mx0, fmaxf(s[n][0], s[n][1]));
            mx1 = fmaxf(mx1, fmaxf(s[n][2], s[n][3]));
        }
        mx0 = fmaxf(mx0, __shfl_xor_sync(0xFFFFFFFFu, mx0, 1));
        mx0 = fmaxf(mx0, __shfl_xor_sync(0xFFFFFFFFu, mx0, 2));
        mx1 = fmaxf(mx1, __shfl_xor_sync(0xFFFFFFFFu, mx1, 1));
        mx1 = fmaxf(mx1, __shfl_xor_sync(0xFFFFFFFFu, mx1, 2));

        const float nm0 = fmaxf(m0, mx0), nm1 = fmaxf(m1, mx1);
        const float cf0 = __expf(m0 - nm0), cf1 = __expf(m1 - nm1);
        l0 *= cf0; l1 *= cf1;
        #pragma unroll
        for (int n = 0; n < 8; n++) {
            o[n][0] *= cf0; o[n][1] *= cf0;
            o[n][2] *= cf1; o[n][3] *= cf1;
        }

        float ps0 = 0.f, ps1 = 0.f;
        for (int n = 0; n <= nmax; n++) {
            const float p0 = __expf(s[n][0] - nm0);
            const float p1 = __expf(s[n][1] - nm0);
            const float p2 = __expf(s[n][2] - nm1);
            const float p3 = __expf(s[n][3] - nm1);
            ps0 += p0 + p1; ps1 += p2 + p3;
            float2 lo; lo.x = f2tf32(p0); lo.y = f2tf32(p1);
            float2 hi; hi.x = f2tf32(p2); hi.y = f2tf32(p3);
            *reinterpret_cast<float2*>(Ps + rowA * KST + n * 8 + 2 * tq) = lo;
            *reinterpret_cast<float2*>(Ps + rowB * KST + n * 8 + 2 * tq) = hi;
        }
        ps0 += __shfl_xor_sync(0xFFFFFFFFu, ps0, 1);
        ps0 += __shfl_xor_sync(0xFFFFFFFFu, ps0, 2);
        ps1 += __shfl_xor_sync(0xFFFFFFFFu, ps1, 1);
        ps1 += __shfl_xor_sync(0xFFFFFFFFu, ps1, 2);
        l0 += ps0; l1 += ps1; m0 = nm0; m1 = nm1;
        __syncwarp();

        for (int k = 0; k <= nmax; k++) {
            const float* pb = Ps + (w * 16) * KST + k * 8 + tq;
            uint32_t pa[4];
            pa[0] = __float_as_uint(pb[gq * KST]);
            pa[1] = __float_as_uint(pb[(gq + 8) * KST]);
            pa[2] = __float_as_uint(pb[gq * KST + 4]);
            pa[3] = __float_as_uint(pb[(gq + 8) * KST + 4]);
            const float* vb = Vs + (k * 8 + tq) * KST + gq;
            #pragma unroll
            for (int n = 0; n < 8; n++) {
                const uint32_t b0 = __float_as_uint(vb[n * 8]);
                const uint32_t b1 = __float_as_uint(vb[4 * KST + n * 8]);
                mma_tf32(o[n], pa, b0, b1);
            }
        }
    }

    const float i0 = 1.f / l0, i1 = 1.f / l1;
    float* dstA = out + (tok0 + rowA) * EE + h * HD;
    float* dstB = out + (tok0 + rowB) * EE + h * HD;
    #pragma unroll
    for (int n = 0; n < 8; n++) {
        float2 a; a.x = o[n][0] * i0; a.y = o[n][1] * i0;
        float2 c; c.x = o[n][2] * i1; c.y = o[n][3] * i1;
        *reinterpret_cast<float2*>(dstA + n * 8 + 2 * tq) = a;
        *reinterpret_cast<float2*>(dstB + n * 8 + 2 * tq) = c;
    }
}

// ---------------------------------------------------------------------------
extern "C" void kernel_launch(void* const* d_in, const int* in_sizes, int n_in,
                              void* d_out, int out_size)
{
    const float* x  = (const float*)d_in[0];  // hidden_states [2,2048,1024]
    const float* Wa = (const float*)d_in[1];  // W_attn [1024,3072]
    const float* ba = (const float*)d_in[2];  // b_attn [3072]
    const float* Wp = (const float*)d_in[3];  // W_proj [1024,1024]
    const float* bp = (const float*)d_in[4];  // b_proj [1024]
    float* out = (float*)d_out;               // [2,2048,1024]

    float *qkv, *att;
    cudaGetSymbolAddress((void**)&qkv, g_qkv);
    cudaGetSymbolAddress((void**)&att, g_att);

    const int gemm_smem = (2 * A_TILE + 2 * B_TILE) * sizeof(float);  // 37888 B
    cudaFuncSetAttribute(gemm_tf32_kernel,
                         cudaFuncAttributeMaxDynamicSharedMemorySize, gemm_smem);

    // 1) QKV projection (single-pass tf32 tensor cores)
    gemm_tf32_kernel<<<dim3(C3 / 128, MTOK / 128), 256, gemm_smem>>>(
        x, Wa, ba, qkv, MTOK, C3, EE);

    // 2) Tensor-core fused causal attention
    const size_t shmem = (size_t)(3 * 64 * KST) * sizeof(float);  // 58368 B
    cudaFuncSetAttribute(attn_tc_kernel, cudaFuncAttributeMaxDynamicSharedMemorySize, (int)shmem);
    attn_tc_kernel<<<dim3(SS / 64, HH, BB), 128, shmem>>>(qkv, att);

    // 3) Output projection (single-pass tf32 tensor cores)
    gemm_tf32_kernel<<<dim3(EE / 128, MTOK / 128), 256, gemm_smem>>>(
        att, Wp, bp, out, MTOK, EE, EE);
}